// round 15
// baseline (speedup 1.0000x reference)
#include <cuda_runtime.h>

#define NN 8192
#define CC 128
#define FULLMASK 0xFFFFFFFFu
#define CAP 128
#define BM 32

// ---- scratch ----
__device__ float g_h[NN * CC];
__device__ int   g_degi[NN];            // zeroed by k_gemm self-clean (static-init first call)
__device__ int   g_cnt[NN];
__device__ int   g_bkt[NN * CAP];
__device__ float g_BT[2 * CC * CC];     // [Wn^T ; Wc^T], K-major [256][128]
__device__ float g_sum[CC];
__device__ float g_sumsq[CC];
// readiness counters (reset by k_norm each iteration)
__device__ int   g_strip_done[16];      // 128 row-chunk blocks each
__device__ int   g_chunk_done[128];     // 16 strip blocks each
__device__ int   g_prep_done;           // 33 tail jobs

__device__ __forceinline__ void ffma2(unsigned long long& d, unsigned long long a, unsigned long long b) {
    asm("fma.rn.f32x2 %0, %1, %2, %0;" : "+l"(d) : "l"(a), "l"(b));
}
__device__ __forceinline__ unsigned long long pack2(float x) {
    unsigned long long r; asm("mov.b64 %0, {%1, %1};" : "=l"(r) : "f"(x)); return r;
}

// ---------------------------------------------------------------
// Kernel 1 (main stream): strip-ordered scan + tail jobs, with
// completion counters so the concurrent gemm can start per-strip.
// Block b<2048: strip = b>>7 (512 cols), chunk = b&127 (64 rows).
// Same proven warp body: warp-task = 32 consecutive uint4 of one row.
__global__ void __launch_bounds__(256, 8)
k_scan(const uint4* __restrict__ A4,
       const float* __restrict__ Wn, const float* __restrict__ Wc) {
    if (blockIdx.x >= 2048) {
        int bid = blockIdx.x - 2048;
        if (bid == 32) {
            if (threadIdx.x < CC) { g_sum[threadIdx.x] = 0.f; g_sumsq[threadIdx.x] = 0.f; }
        } else {
            __shared__ float s[32][33];
            int m = bid >> 4;
            int t = bid & 15;
            int tr = (t >> 2) * 32;
            int tc = (t & 3) * 32;
            const float* src = m ? Wc : Wn;
            float* dst = g_BT + m * CC * CC;
            int x = threadIdx.x & 31;
            int y0 = threadIdx.x >> 5;
#pragma unroll
            for (int dy = 0; dy < 32; dy += 8)
                s[y0 + dy][x] = src[(tr + y0 + dy) * CC + tc + x];
            __syncthreads();
#pragma unroll
            for (int dy = 0; dy < 32; dy += 8)
                dst[(tc + y0 + dy) * CC + tr + x] = s[x][y0 + dy];
        }
        __syncthreads();
        __threadfence();
        if (threadIdx.x == 0) atomicAdd(&g_prep_done, 1);
        return;
    }

    const int strip = blockIdx.x >> 7;       // 0..15
    const int chunk = blockIdx.x & 127;      // 0..127
    const int r0 = chunk * 64;
    const int cbu = strip * 128;             // uint4 offset within row
    const int lane = threadIdx.x & 31;
    const int w = threadIdx.x >> 5;          // 8 warps

#pragma unroll 1
    for (int i = 0; i < 32; i += 4) {
        uint4 v[4];
        int tt[4];
#pragma unroll
        for (int k = 0; k < 4; ++k) {
            int t = w + (i + k) * 8;         // warp-task 0..255
            tt[k] = t;
            int r = t >> 2, ch = t & 3;
            v[k] = __ldcs(&A4[(unsigned)(r0 + r) * 2048u + cbu + ch * 32 + lane]);
        }
#pragma unroll
        for (int k = 0; k < 4; ++k) {
            unsigned nz = v[k].x | v[k].y | v[k].z | v[k].w;
            unsigned anyb = __ballot_sync(FULLMASK, nz != 0u);
            if (!anyb) continue;
            int t = tt[k];
            int j = r0 + (t >> 2);
            int cnt = (v[k].x != 0u) + (v[k].y != 0u) + (v[k].z != 0u) + (v[k].w != 0u);
            int tot = __reduce_add_sync(FULLMASK, cnt);
            if (lane == 0) atomicAdd(&g_degi[j], tot);
            if (nz) {
                int col0 = strip * 512 + (t & 3) * 128 + lane * 4;
                unsigned vv[4] = {v[k].x, v[k].y, v[k].z, v[k].w};
#pragma unroll
                for (int s = 0; s < 4; ++s) {
                    if (vv[s]) {
                        int i2 = col0 + s;
                        int pos = atomicAdd(&g_cnt[i2], 1);
                        if (pos < CAP) g_bkt[i2 * CAP + pos] = j;
                    }
                }
            }
        }
    }
    __syncthreads();
    __threadfence();
    if (threadIdx.x == 0) {
        atomicAdd(&g_strip_done[strip], 1);
        atomicAdd(&g_chunk_done[chunk], 1);
    }
}

// ---------------------------------------------------------------
// Kernel 2 (stream 2, concurrent): spin until this block's strip/chunk
// are scanned, then R13's proven gather + GEMM + BN-stat epilogue.
__global__ void __launch_bounds__(256, 2)
k_gemm(const float* __restrict__ X, const float* __restrict__ bn, const float* __restrict__ bc) {
    extern __shared__ float sh[];
    float* Bs = sh;                  // 16384 floats (64KB)
    float* As = sh + CC * CC;        // 4096 floats (16KB)

    const int tid  = threadIdx.x;
    const int lane = tid & 31;
    const int wid  = tid >> 5;
    const int m0   = blockIdx.x * BM;
    const int strip = blockIdx.x >> 4;   // m0/512
    const int chunk = blockIdx.x >> 1;   // m0/64

    // --- wait for readiness (scan runs concurrently on another stream) ---
    if (tid == 0) {
        while (*(volatile int*)&g_strip_done[strip] < 128 ||
               *(volatile int*)&g_chunk_done[chunk] < 16 ||
               *(volatile int*)&g_prep_done < 33)
            __nanosleep(128);
        __threadfence();
    }
    __syncthreads();

    {
        const float4* src = (const float4*)g_BT;
        float4* dst = (float4*)Bs;
#pragma unroll
        for (int i = 0; i < 16; ++i) dst[tid + i * 256] = src[tid + i * 256];
    }

    // --- gather: warp handles rows wid*4..+3, two rows at a time (MLP 8) ---
    const float4* X4 = (const float4*)X;
#pragma unroll 1
    for (int rp = 0; rp < 4; rp += 2) {
        const int rowA = wid * 4 + rp, rowB = rowA + 1;
        const int nodeA = m0 + rowA,   nodeB = m0 + rowB;
        int cA = g_cnt[nodeA]; cA = cA > CAP ? CAP : cA;
        int cB = g_cnt[nodeB]; cB = cB > CAP ? CAP : cB;
        int dA = g_degi[nodeA], dB = g_degi[nodeB];
        float rA = (dA > 0) ? (1.f / (float)dA) : 1.f;
        float rB = (dB > 0) ? (1.f / (float)dB) : 1.f;
        const int* bkA = g_bkt + nodeA * CAP;
        const int* bkB = g_bkt + nodeB * CAP;

        int nbA[4], nbB[4];
#pragma unroll
        for (int w = 0; w < 4; ++w) {
            nbA[w] = (lane + 32 * w < cA) ? bkA[lane + 32 * w] : 0;
            nbB[w] = (lane + 32 * w < cB) ? bkB[lane + 32 * w] : 0;
        }

        float4 aA = {0.f, 0.f, 0.f, 0.f};
        float4 aB = {0.f, 0.f, 0.f, 0.f};
        const int mm = (cA < cB ? cA : cB) & ~3;
        int t = 0;
        for (; t < mm; t += 4) {
            int ja0 = __shfl_sync(FULLMASK, nbA[(t + 0) >> 5], (t + 0) & 31);
            int ja1 = __shfl_sync(FULLMASK, nbA[(t + 1) >> 5], (t + 1) & 31);
            int ja2 = __shfl_sync(FULLMASK, nbA[(t + 2) >> 5], (t + 2) & 31);
            int ja3 = __shfl_sync(FULLMASK, nbA[(t + 3) >> 5], (t + 3) & 31);
            int jb0 = __shfl_sync(FULLMASK, nbB[(t + 0) >> 5], (t + 0) & 31);
            int jb1 = __shfl_sync(FULLMASK, nbB[(t + 1) >> 5], (t + 1) & 31);
            int jb2 = __shfl_sync(FULLMASK, nbB[(t + 2) >> 5], (t + 2) & 31);
            int jb3 = __shfl_sync(FULLMASK, nbB[(t + 3) >> 5], (t + 3) & 31);
            float4 x0 = __ldg(X4 + (long)ja0 * 32 + lane);
            float4 x1 = __ldg(X4 + (long)ja1 * 32 + lane);
            float4 x2 = __ldg(X4 + (long)ja2 * 32 + lane);
            float4 x3 = __ldg(X4 + (long)ja3 * 32 + lane);
            float4 y0 = __ldg(X4 + (long)jb0 * 32 + lane);
            float4 y1 = __ldg(X4 + (long)jb1 * 32 + lane);
            float4 y2 = __ldg(X4 + (long)jb2 * 32 + lane);
            float4 y3 = __ldg(X4 + (long)jb3 * 32 + lane);
            aA.x += x0.x + x1.x + x2.x + x3.x;
            aA.y += x0.y + x1.y + x2.y + x3.y;
            aA.z += x0.z + x1.z + x2.z + x3.z;
            aA.w += x0.w + x1.w + x2.w + x3.w;
            aB.x += y0.x + y1.x + y2.x + y3.x;
            aB.y += y0.y + y1.y + y2.y + y3.y;
            aB.z += y0.z + y1.z + y2.z + y3.z;
            aB.w += y0.w + y1.w + y2.w + y3.w;
        }
        int tB = t;
        for (; t + 4 <= cA; t += 4) {
            int j0 = __shfl_sync(FULLMASK, nbA[(t + 0) >> 5], (t + 0) & 31);
            int j1 = __shfl_sync(FULLMASK, nbA[(t + 1) >> 5], (t + 1) & 31);
            int j2 = __shfl_sync(FULLMASK, nbA[(t + 2) >> 5], (t + 2) & 31);
            int j3 = __shfl_sync(FULLMASK, nbA[(t + 3) >> 5], (t + 3) & 31);
            float4 x0 = __ldg(X4 + (long)j0 * 32 + lane);
            float4 x1 = __ldg(X4 + (long)j1 * 32 + lane);
            float4 x2 = __ldg(X4 + (long)j2 * 32 + lane);
            float4 x3 = __ldg(X4 + (long)j3 * 32 + lane);
            aA.x += x0.x + x1.x + x2.x + x3.x;
            aA.y += x0.y + x1.y + x2.y + x3.y;
            aA.z += x0.z + x1.z + x2.z + x3.z;
            aA.w += x0.w + x1.w + x2.w + x3.w;
        }
        for (; t < cA; ++t) {
            int j = __shfl_sync(FULLMASK, nbA[t >> 5], t & 31);
            float4 x = __ldg(X4 + (long)j * 32 + lane);
            aA.x += x.x; aA.y += x.y; aA.z += x.z; aA.w += x.w;
        }
        for (; tB + 4 <= cB; tB += 4) {
            int j0 = __shfl_sync(FULLMASK, nbB[(tB + 0) >> 5], (tB + 0) & 31);
            int j1 = __shfl_sync(FULLMASK, nbB[(tB + 1) >> 5], (tB + 1) & 31);
            int j2 = __shfl_sync(FULLMASK, nbB[(tB + 2) >> 5], (tB + 2) & 31);
            int j3 = __shfl_sync(FULLMASK, nbB[(tB + 3) >> 5], (tB + 3) & 31);
            float4 y0 = __ldg(X4 + (long)j0 * 32 + lane);
            float4 y1 = __ldg(X4 + (long)j1 * 32 + lane);
            float4 y2 = __ldg(X4 + (long)j2 * 32 + lane);
            float4 y3 = __ldg(X4 + (long)j3 * 32 + lane);
            aB.x += y0.x + y1.x + y2.x + y3.x;
            aB.y += y0.y + y1.y + y2.y + y3.y;
            aB.z += y0.z + y1.z + y2.z + y3.z;
            aB.w += y0.w + y1.w + y2.w + y3.w;
        }
        for (; tB < cB; ++tB) {
            int j = __shfl_sync(FULLMASK, nbB[tB >> 5], tB & 31);
            float4 y = __ldg(X4 + (long)j * 32 + lane);
            aB.x += y.x; aB.y += y.y; aB.z += y.z; aB.w += y.w;
        }
        aA.x *= rA; aA.y *= rA; aA.z *= rA; aA.w *= rA;
        aB.x *= rB; aB.y *= rB; aB.z *= rB; aB.w *= rB;
        *(float4*)(As + (size_t)rowA * CC + lane * 4) = aA;
        *(float4*)(As + (size_t)rowB * CC + lane * 4) = aB;
    }
    if (lane < 4) {
        int node = m0 + wid * 4 + lane;
        g_cnt[node] = 0;
        g_degi[node] = 0;
    }
    __syncthreads();

    const int cg = tid & 31;
    const int rg = tid >> 5;
    unsigned long long acc[4][2];
#pragma unroll
    for (int r = 0; r < 4; ++r) { acc[r][0] = 0ull; acc[r][1] = 0ull; }

#pragma unroll 1
    for (int half = 0; half < 2; ++half) {
        const float* bb = Bs + cg * 4;
        const float* ab = As + rg * 4 * CC;
#pragma unroll 2
        for (int kk = 0; kk < CC; kk += 4) {
            float4 a[4];
#pragma unroll
            for (int r = 0; r < 4; ++r) a[r] = *(const float4*)(ab + r * CC + kk);
#pragma unroll
            for (int j = 0; j < 4; ++j) {
                ulonglong2 bp = *(const ulonglong2*)(bb + (kk + j) * CC);
                float av[4];
#pragma unroll
                for (int r = 0; r < 4; ++r)
                    av[r] = (j == 0) ? a[r].x : (j == 1) ? a[r].y : (j == 2) ? a[r].z : a[r].w;
#pragma unroll
                for (int r = 0; r < 4; ++r) {
                    unsigned long long ad = pack2(av[r]);
                    ffma2(acc[r][0], ad, bp.x);
                    ffma2(acc[r][1], ad, bp.y);
                }
            }
        }
        if (half == 0) {
            __syncthreads();
            const float4* wsrc = (const float4*)(g_BT + CC * CC);
            float4* wdst = (float4*)Bs;
#pragma unroll
            for (int i = 0; i < 16; ++i) wdst[tid + i * 256] = wsrc[tid + i * 256];
            const float4* xs = (const float4*)(X + (size_t)m0 * CC);
            float4* ad = (float4*)As;
#pragma unroll
            for (int i = 0; i < 4; ++i) ad[tid + i * 256] = __ldg(xs + tid + i * 256);
            __syncthreads();
        }
    }

    __syncthreads();
    float* s_sum = sh;
    float* s_sq  = sh + CC;
    if (tid < CC) { s_sum[tid] = 0.f; s_sq[tid] = 0.f; }
    __syncthreads();

    float bias[4];
#pragma unroll
    for (int c = 0; c < 4; ++c) bias[c] = __ldg(bn + cg * 4 + c) + __ldg(bc + cg * 4 + c);

    float psum[4] = {0, 0, 0, 0};
    float psq[4]  = {0, 0, 0, 0};
#pragma unroll
    for (int r = 0; r < 4; ++r) {
        int m = m0 + rg * 4 + r;
        float2 p0 = *(float2*)&acc[r][0];
        float2 p1 = *(float2*)&acc[r][1];
        float h[4] = {p0.x + bias[0], p0.y + bias[1], p1.x + bias[2], p1.y + bias[3]};
#pragma unroll
        for (int c = 0; c < 4; ++c) { psum[c] += h[c]; psq[c] += h[c] * h[c]; }
        float4 hv = {h[0], h[1], h[2], h[3]};
        *(float4*)(g_h + (size_t)m * CC + cg * 4) = hv;
    }
#pragma unroll
    for (int c = 0; c < 4; ++c) {
        atomicAdd(&s_sum[cg * 4 + c], psum[c]);
        atomicAdd(&s_sq[cg * 4 + c],  psq[c]);
    }
    __syncthreads();
    if (tid < CC) {
        atomicAdd(&g_sum[tid],   s_sum[tid]);
        atomicAdd(&g_sumsq[tid], s_sq[tid]);
    }
}

// ---------------------------------------------------------------
// Kernel 3 (stream 2, after gemm): scale/shift + normalize + counter reset.
__global__ void k_norm(const float* __restrict__ gamma, const float* __restrict__ beta,
                       float* __restrict__ out) {
    __shared__ float s_sc[CC], s_sf[CC];
    const int tid = threadIdx.x;
    if (blockIdx.x == 0) {       // reset readiness counters for next replay
        if (tid < 16) g_strip_done[tid] = 0;
        if (tid < 128) g_chunk_done[tid] = 0;
        if (tid == 0) g_prep_done = 0;
    }
    if (tid < CC) {
        const float invN = 1.f / (float)NN;
        float mu  = g_sum[tid] * invN;
        float var = fmaxf(g_sumsq[tid] * invN - mu * mu, 0.f);
        float inv = rsqrtf(var + 1e-5f);
        float sc = __ldg(gamma + tid) * inv;
        s_sc[tid] = sc;
        s_sf[tid] = __ldg(beta + tid) - mu * sc;
    }
    __syncthreads();

    const int gtid = blockIdx.x * blockDim.x + tid;
    const int c0 = (gtid & 31) * 4;
    float4 sc = *(const float4*)(s_sc + c0);
    float4 sf = *(const float4*)(s_sf + c0);
    const float4* hp = (const float4*)g_h;
    float4* op = (float4*)out;
#pragma unroll
    for (int u = 0; u < 2; ++u) {
        int idx = gtid + u * 131072;
        float4 h = __ldcs(hp + idx);
        float4 o;
        o.x = fmaxf(fmaf(h.x, sc.x, sf.x), 0.f);
        o.y = fmaxf(fmaf(h.y, sc.y, sf.y), 0.f);
        o.z = fmaxf(fmaf(h.z, sc.z, sf.z), 0.f);
        o.w = fmaxf(fmaf(h.w, sc.w, sf.w), 0.f);
        op[idx] = o;
    }
}

// ---------------------------------------------------------------
extern "C" void kernel_launch(void* const* d_in, const int* in_sizes, int n_in,
                              void* d_out, int out_size) {
    const float* Xf    = (const float*)d_in[0];
    const float* A     = (const float*)d_in[1];
    const float* Wn    = (const float*)d_in[2];
    const float* bn    = (const float*)d_in[3];
    const float* Wc    = (const float*)d_in[4];
    const float* bc    = (const float*)d_in[5];
    const float* gamma = (const float*)d_in[6];
    const float* beta  = (const float*)d_in[7];
    if (in_sizes[0] > in_sizes[1]) { const float* t = Xf; Xf = A; A = t; }

    float* out = (float*)d_out;

    static cudaStream_t s2 = []() {
        cudaStream_t s;
        int lo, hi;
        cudaDeviceGetStreamPriorityRange(&lo, &hi);
        cudaStreamCreateWithPriority(&s, cudaStreamNonBlocking, hi);  // high priority
        return s;
    }();
    static cudaEvent_t evF = []() {
        cudaEvent_t e; cudaEventCreateWithFlags(&e, cudaEventDisableTiming); return e;
    }();
    static cudaEvent_t evJ = []() {
        cudaEvent_t e; cudaEventCreateWithFlags(&e, cudaEventDisableTiming); return e;
    }();
    static bool attr_done = []() {
        size_t smem = (size_t)(CC * CC + BM * CC) * sizeof(float);   // 80KB
        cudaFuncSetAttribute(k_gemm, cudaFuncAttributeMaxDynamicSharedMemorySize, (int)smem);
        return true;
    }();
    (void)attr_done;

    const size_t smem = (size_t)(CC * CC + BM * CC) * sizeof(float);

    // fork: gemm+norm on s2 (they self-synchronize with the scan via counters)
    cudaEventRecord(evF, 0);
    cudaStreamWaitEvent(s2, evF, 0);

    k_scan<<<2048 + 33, 256>>>((const uint4*)A, Wn, Wc);          // main stream
    k_gemm<<<NN / BM, 256, smem, s2>>>(Xf, bn, bc);               // concurrent
    k_norm<<<512, 256, 0, s2>>>(gamma, beta, out);

    cudaEventRecord(evJ, s2);
    cudaStreamWaitEvent(0, evJ, 0);
}

// round 16
// speedup vs baseline: 1.1850x; 1.1850x over previous
#include <cuda_runtime.h>
#include <cuda_fp16.h>

#define NN 8192
#define CC 128
#define FULLMASK 0xFFFFFFFFu
#define CAP 128
#define BM 32
#define SCANB 2048

// ---- scratch ----
__device__ float  g_h[NN * CC];
__device__ __half g_x16[NN * CC];       // fp16 copy of X for the gather
__device__ int    g_degi[NN];           // zeroed by k_gemm self-clean (static-init first call)
__device__ int    g_cnt[NN];
__device__ int    g_bkt[NN * CAP];
__device__ float  g_BT[2 * CC * CC];    // [Wn^T ; Wc^T], K-major [256][128]
__device__ float  g_sum[CC];            // zeroed by scan tail block
__device__ float  g_sumsq[CC];

__device__ __forceinline__ void ffma2(unsigned long long& d, unsigned long long a, unsigned long long b) {
    asm("fma.rn.f32x2 %0, %1, %2, %0;" : "+l"(d) : "l"(a), "l"(b));
}
__device__ __forceinline__ unsigned long long pack2(float x) {
    unsigned long long r; asm("mov.b64 %0, {%1, %1};" : "=l"(r) : "f"(x)); return r;
}

// ---------------------------------------------------------------
// Kernel 1: scan (blocks 0..2047, R13-proven) + tails:
//   2048..2079 weight transpose, 2080 stat zero, 2081..2112 X->fp16.
__global__ void __launch_bounds__(256, 8)
k_scan(const uint4* __restrict__ A4,
       const float* __restrict__ Wn, const float* __restrict__ Wc,
       const float4* __restrict__ X4) {
    if (blockIdx.x >= SCANB) {
        int bid = blockIdx.x - SCANB;
        if (bid < 32) {
            __shared__ float s[32][33];
            int m = bid >> 4;
            int t = bid & 15;
            int tr = (t >> 2) * 32;
            int tc = (t & 3) * 32;
            const float* src = m ? Wc : Wn;
            float* dst = g_BT + m * CC * CC;
            int x = threadIdx.x & 31;
            int y0 = threadIdx.x >> 5;
#pragma unroll
            for (int dy = 0; dy < 32; dy += 8)
                s[y0 + dy][x] = src[(tr + y0 + dy) * CC + tc + x];
            __syncthreads();
#pragma unroll
            for (int dy = 0; dy < 32; dy += 8)
                dst[(tc + y0 + dy) * CC + tr + x] = s[x][y0 + dy];
        } else if (bid == 32) {
            if (threadIdx.x < CC) { g_sum[threadIdx.x] = 0.f; g_sumsq[threadIdx.x] = 0.f; }
        } else {
            // X -> fp16 copy: 32 blocks x 8192 float4
            int base = (bid - 33) * 8192 + threadIdx.x;
            uint2* dst = (uint2*)g_x16;
#pragma unroll
            for (int k = 0; k < 32; ++k) {
                int idx = base + k * 256;
                float4 v = __ldg(X4 + idx);
                __half2 h01 = __floats2half2_rn(v.x, v.y);
                __half2 h23 = __floats2half2_rn(v.z, v.w);
                uint2 p;
                p.x = *(unsigned*)&h01;
                p.y = *(unsigned*)&h23;
                dst[idx] = p;
            }
        }
        return;
    }

    const int lane = threadIdx.x & 31;
    const unsigned stride = SCANB * 256u;      // 524288 uint4
    unsigned q0 = blockIdx.x * 256u + threadIdx.x;

#pragma unroll 1
    for (int it = 0; it < 8; ++it, q0 += 4u * stride) {
        uint4 v[4];
#pragma unroll
        for (int u = 0; u < 4; ++u) v[u] = __ldcs(&A4[q0 + u * stride]);
#pragma unroll
        for (int u = 0; u < 4; ++u) {
            unsigned nz = v[u].x | v[u].y | v[u].z | v[u].w;
            unsigned anyb = __ballot_sync(FULLMASK, nz != 0u);
            if (!anyb) continue;
            unsigned qu = q0 + u * stride;
            int j = (int)(qu >> 11);
            int cnt = (v[u].x != 0u) + (v[u].y != 0u) + (v[u].z != 0u) + (v[u].w != 0u);
            int tot = __reduce_add_sync(FULLMASK, cnt);
            if (lane == 0) atomicAdd(&g_degi[j], tot);
            if (nz) {
                unsigned cbase = (qu & 2047u) * 4u;
                unsigned vv[4] = {v[u].x, v[u].y, v[u].z, v[u].w};
#pragma unroll
                for (int s = 0; s < 4; ++s) {
                    if (vv[s]) {
                        unsigned i = cbase + s;
                        int pos = atomicAdd(&g_cnt[i], 1);
                        if (pos < CAP) g_bkt[i * CAP + pos] = j;
                    }
                }
            }
        }
    }
}

// ---------------------------------------------------------------
// fp16 row accumulate helper: adds X16[j] (4 channels at lane) into acc
__device__ __forceinline__ void acc_h4(float4& a, uint2 p) {
    float2 lo = __half22float2(*(__half2*)&p.x);
    float2 hi = __half22float2(*(__half2*)&p.y);
    a.x += lo.x; a.y += lo.y; a.z += hi.x; a.w += hi.y;
}

// ---------------------------------------------------------------
// Kernel 2: fused gather (fp16 X, MLP 8) + GEMM + BN stats + self-clean.
__global__ void __launch_bounds__(256, 2)
k_gemm(const float* __restrict__ X, const float* __restrict__ bn, const float* __restrict__ bc) {
    extern __shared__ float sh[];
    float* Bs = sh;                  // 16384 floats (64KB) — current weight half
    float* As = sh + CC * CC;        // 4096 floats (16KB) — 32-row A tile

    const int tid  = threadIdx.x;
    const int lane = tid & 31;
    const int wid  = tid >> 5;       // 8 warps
    const int m0   = blockIdx.x * BM;

    {
        const float4* src = (const float4*)g_BT;
        float4* dst = (float4*)Bs;
#pragma unroll
        for (int i = 0; i < 16; ++i) dst[tid + i * 256] = src[tid + i * 256];
    }

    // --- gather: warp handles rows wid*4..+3, two rows at a time (MLP 8) ---
    const uint2* H2 = (const uint2*)g_x16;
#pragma unroll 1
    for (int rp = 0; rp < 4; rp += 2) {
        const int rowA = wid * 4 + rp, rowB = rowA + 1;
        const int nodeA = m0 + rowA,   nodeB = m0 + rowB;
        int cA = g_cnt[nodeA]; cA = cA > CAP ? CAP : cA;
        int cB = g_cnt[nodeB]; cB = cB > CAP ? CAP : cB;
        int dA = g_degi[nodeA], dB = g_degi[nodeB];
        float rA = (dA > 0) ? (1.f / (float)dA) : 1.f;
        float rB = (dB > 0) ? (1.f / (float)dB) : 1.f;
        const int* bkA = g_bkt + nodeA * CAP;
        const int* bkB = g_bkt + nodeB * CAP;

        int nbA[4], nbB[4];
#pragma unroll
        for (int w = 0; w < 4; ++w) {
            nbA[w] = (lane + 32 * w < cA) ? bkA[lane + 32 * w] : 0;
            nbB[w] = (lane + 32 * w < cB) ? bkB[lane + 32 * w] : 0;
        }

        float4 aA = {0.f, 0.f, 0.f, 0.f};
        float4 aB = {0.f, 0.f, 0.f, 0.f};
        const int mm = (cA < cB ? cA : cB) & ~3;
        int t = 0;
        for (; t < mm; t += 4) {            // 8 loads in flight
            int ja0 = __shfl_sync(FULLMASK, nbA[(t + 0) >> 5], (t + 0) & 31);
            int ja1 = __shfl_sync(FULLMASK, nbA[(t + 1) >> 5], (t + 1) & 31);
            int ja2 = __shfl_sync(FULLMASK, nbA[(t + 2) >> 5], (t + 2) & 31);
            int ja3 = __shfl_sync(FULLMASK, nbA[(t + 3) >> 5], (t + 3) & 31);
            int jb0 = __shfl_sync(FULLMASK, nbB[(t + 0) >> 5], (t + 0) & 31);
            int jb1 = __shfl_sync(FULLMASK, nbB[(t + 1) >> 5], (t + 1) & 31);
            int jb2 = __shfl_sync(FULLMASK, nbB[(t + 2) >> 5], (t + 2) & 31);
            int jb3 = __shfl_sync(FULLMASK, nbB[(t + 3) >> 5], (t + 3) & 31);
            uint2 x0 = __ldg(H2 + (long)ja0 * 32 + lane);
            uint2 x1 = __ldg(H2 + (long)ja1 * 32 + lane);
            uint2 x2 = __ldg(H2 + (long)ja2 * 32 + lane);
            uint2 x3 = __ldg(H2 + (long)ja3 * 32 + lane);
            uint2 y0 = __ldg(H2 + (long)jb0 * 32 + lane);
            uint2 y1 = __ldg(H2 + (long)jb1 * 32 + lane);
            uint2 y2 = __ldg(H2 + (long)jb2 * 32 + lane);
            uint2 y3 = __ldg(H2 + (long)jb3 * 32 + lane);
            acc_h4(aA, x0); acc_h4(aA, x1); acc_h4(aA, x2); acc_h4(aA, x3);
            acc_h4(aB, y0); acc_h4(aB, y1); acc_h4(aB, y2); acc_h4(aB, y3);
        }
        int tB = t;
        for (; t + 4 <= cA; t += 4) {
            int j0 = __shfl_sync(FULLMASK, nbA[(t + 0) >> 5], (t + 0) & 31);
            int j1 = __shfl_sync(FULLMASK, nbA[(t + 1) >> 5], (t + 1) & 31);
            int j2 = __shfl_sync(FULLMASK, nbA[(t + 2) >> 5], (t + 2) & 31);
            int j3 = __shfl_sync(FULLMASK, nbA[(t + 3) >> 5], (t + 3) & 31);
            uint2 x0 = __ldg(H2 + (long)j0 * 32 + lane);
            uint2 x1 = __ldg(H2 + (long)j1 * 32 + lane);
            uint2 x2 = __ldg(H2 + (long)j2 * 32 + lane);
            uint2 x3 = __ldg(H2 + (long)j3 * 32 + lane);
            acc_h4(aA, x0); acc_h4(aA, x1); acc_h4(aA, x2); acc_h4(aA, x3);
        }
        for (; t < cA; ++t) {
            int j = __shfl_sync(FULLMASK, nbA[t >> 5], t & 31);
            acc_h4(aA, __ldg(H2 + (long)j * 32 + lane));
        }
        for (; tB + 4 <= cB; tB += 4) {
            int j0 = __shfl_sync(FULLMASK, nbB[(tB + 0) >> 5], (tB + 0) & 31);
            int j1 = __shfl_sync(FULLMASK, nbB[(tB + 1) >> 5], (tB + 1) & 31);
            int j2 = __shfl_sync(FULLMASK, nbB[(tB + 2) >> 5], (tB + 2) & 31);
            int j3 = __shfl_sync(FULLMASK, nbB[(tB + 3) >> 5], (tB + 3) & 31);
            uint2 y0 = __ldg(H2 + (long)j0 * 32 + lane);
            uint2 y1 = __ldg(H2 + (long)j1 * 32 + lane);
            uint2 y2 = __ldg(H2 + (long)j2 * 32 + lane);
            uint2 y3 = __ldg(H2 + (long)j3 * 32 + lane);
            acc_h4(aB, y0); acc_h4(aB, y1); acc_h4(aB, y2); acc_h4(aB, y3);
        }
        for (; tB < cB; ++tB) {
            int j = __shfl_sync(FULLMASK, nbB[tB >> 5], tB & 31);
            acc_h4(aB, __ldg(H2 + (long)j * 32 + lane));
        }
        aA.x *= rA; aA.y *= rA; aA.z *= rA; aA.w *= rA;
        aB.x *= rB; aB.y *= rB; aB.z *= rB; aB.w *= rB;
        *(float4*)(As + (size_t)rowA * CC + lane * 4) = aA;
        *(float4*)(As + (size_t)rowB * CC + lane * 4) = aB;
    }
    if (lane < 4) {
        int node = m0 + wid * 4 + lane;
        g_cnt[node] = 0;
        g_degi[node] = 0;
    }
    __syncthreads();

    const int cg = tid & 31;
    const int rg = tid >> 5;
    unsigned long long acc[4][2];
#pragma unroll
    for (int r = 0; r < 4; ++r) { acc[r][0] = 0ull; acc[r][1] = 0ull; }

#pragma unroll 1
    for (int half = 0; half < 2; ++half) {
        const float* bb = Bs + cg * 4;
        const float* ab = As + rg * 4 * CC;
#pragma unroll 2
        for (int kk = 0; kk < CC; kk += 4) {
            float4 a[4];
#pragma unroll
            for (int r = 0; r < 4; ++r) a[r] = *(const float4*)(ab + r * CC + kk);
#pragma unroll
            for (int j = 0; j < 4; ++j) {
                ulonglong2 bp = *(const ulonglong2*)(bb + (kk + j) * CC);
                float av[4];
#pragma unroll
                for (int r = 0; r < 4; ++r)
                    av[r] = (j == 0) ? a[r].x : (j == 1) ? a[r].y : (j == 2) ? a[r].z : a[r].w;
#pragma unroll
                for (int r = 0; r < 4; ++r) {
                    unsigned long long ad = pack2(av[r]);
                    ffma2(acc[r][0], ad, bp.x);
                    ffma2(acc[r][1], ad, bp.y);
                }
            }
        }
        if (half == 0) {
            __syncthreads();
            const float4* wsrc = (const float4*)(g_BT + CC * CC);
            float4* wdst = (float4*)Bs;
#pragma unroll
            for (int i = 0; i < 16; ++i) wdst[tid + i * 256] = wsrc[tid + i * 256];
            const float4* xs = (const float4*)(X + (size_t)m0 * CC);  // fp32 X for dense half
            float4* ad = (float4*)As;
#pragma unroll
            for (int i = 0; i < 4; ++i) ad[tid + i * 256] = __ldg(xs + tid + i * 256);
            __syncthreads();
        }
    }

    __syncthreads();
    float* s_sum = sh;
    float* s_sq  = sh + CC;
    if (tid < CC) { s_sum[tid] = 0.f; s_sq[tid] = 0.f; }
    __syncthreads();

    float bias[4];
#pragma unroll
    for (int c = 0; c < 4; ++c) bias[c] = __ldg(bn + cg * 4 + c) + __ldg(bc + cg * 4 + c);

    float psum[4] = {0, 0, 0, 0};
    float psq[4]  = {0, 0, 0, 0};
#pragma unroll
    for (int r = 0; r < 4; ++r) {
        int m = m0 + rg * 4 + r;
        float2 p0 = *(float2*)&acc[r][0];
        float2 p1 = *(float2*)&acc[r][1];
        float h[4] = {p0.x + bias[0], p0.y + bias[1], p1.x + bias[2], p1.y + bias[3]};
#pragma unroll
        for (int c = 0; c < 4; ++c) { psum[c] += h[c]; psq[c] += h[c] * h[c]; }
        float4 hv = {h[0], h[1], h[2], h[3]};
        *(float4*)(g_h + (size_t)m * CC + cg * 4) = hv;
    }
#pragma unroll
    for (int c = 0; c < 4; ++c) {
        atomicAdd(&s_sum[cg * 4 + c], psum[c]);
        atomicAdd(&s_sq[cg * 4 + c],  psq[c]);
    }
    __syncthreads();
    if (tid < CC) {
        atomicAdd(&g_sum[tid],   s_sum[tid]);
        atomicAdd(&g_sumsq[tid], s_sq[tid]);
    }
}

// ---------------------------------------------------------------
// Kernel 3: per-block scale/shift from BN stats (L2-hot) + normalize.
__global__ void k_norm(const float* __restrict__ gamma, const float* __restrict__ beta,
                       float* __restrict__ out) {
    __shared__ float s_sc[CC], s_sf[CC];
    const int tid = threadIdx.x;
    if (tid < CC) {
        const float invN = 1.f / (float)NN;
        float mu  = g_sum[tid] * invN;
        float var = fmaxf(g_sumsq[tid] * invN - mu * mu, 0.f);
        float inv = rsqrtf(var + 1e-5f);
        float sc = __ldg(gamma + tid) * inv;
        s_sc[tid] = sc;
        s_sf[tid] = __ldg(beta + tid) - mu * sc;
    }
    __syncthreads();

    const int gtid = blockIdx.x * blockDim.x + tid;
    const int c0 = (gtid & 31) * 4;
    float4 sc = *(const float4*)(s_sc + c0);
    float4 sf = *(const float4*)(s_sf + c0);
    const float4* hp = (const float4*)g_h;
    float4* op = (float4*)out;
#pragma unroll
    for (int u = 0; u < 2; ++u) {
        int idx = gtid + u * 131072;
        float4 h = __ldcs(hp + idx);
        float4 o;
        o.x = fmaxf(fmaf(h.x, sc.x, sf.x), 0.f);
        o.y = fmaxf(fmaf(h.y, sc.y, sf.y), 0.f);
        o.z = fmaxf(fmaf(h.z, sc.z, sf.z), 0.f);
        o.w = fmaxf(fmaf(h.w, sc.w, sf.w), 0.f);
        op[idx] = o;
    }
}

// ---------------------------------------------------------------
extern "C" void kernel_launch(void* const* d_in, const int* in_sizes, int n_in,
                              void* d_out, int out_size) {
    const float* Xf    = (const float*)d_in[0];
    const float* A     = (const float*)d_in[1];
    const float* Wn    = (const float*)d_in[2];
    const float* bn    = (const float*)d_in[3];
    const float* Wc    = (const float*)d_in[4];
    const float* bc    = (const float*)d_in[5];
    const float* gamma = (const float*)d_in[6];
    const float* beta  = (const float*)d_in[7];
    if (in_sizes[0] > in_sizes[1]) { const float* t = Xf; Xf = A; A = t; }

    float* out = (float*)d_out;

    static bool attr_done = []() {
        size_t smem = (size_t)(CC * CC + BM * CC) * sizeof(float);   // 80KB
        cudaFuncSetAttribute(k_gemm, cudaFuncAttributeMaxDynamicSharedMemorySize, (int)smem);
        return true;
    }();
    (void)attr_done;

    const size_t smem = (size_t)(CC * CC + BM * CC) * sizeof(float);

    k_scan<<<SCANB + 65, 256>>>((const uint4*)A, Wn, Wc, (const float4*)Xf);
    k_gemm<<<NN / BM, 256, smem>>>(Xf, bn, bc);
    k_norm<<<512, 256>>>(gamma, beta, out);
}

// round 17
// speedup vs baseline: 1.3942x; 1.1766x over previous
#include <cuda_runtime.h>
#include <cuda_fp16.h>
#include <mma.h>

using namespace nvcuda;

#define NN 8192
#define CC 128
#define FULLMASK 0xFFFFFFFFu
#define CAP 128
#define BM 32
#define SCANB 2048

#define AK_LD 264            // A tile stride (halves): 256 + 8 pad
#define B_LD  136            // B tile stride (halves): 128 + 8 pad
#define C_LD  132            // C tile stride (floats): 128 + 4 pad
#define B_BYTES (256 * B_LD * 2)     // 69632
#define A_BYTES (32 * AK_LD * 2)     // 16896
#define SMEM_TOTAL (B_BYTES + A_BYTES)

// ---- scratch ----
__device__ float  g_h[NN * CC];
__device__ __half g_x16[NN * CC];       // fp16 copy of X
__device__ int    g_degi[NN];           // zeroed by k_gemm self-clean (static-init first call)
__device__ int    g_cnt[NN];
__device__ int    g_bkt[NN * CAP];
__device__ __half g_BTh[2 * CC * CC];   // fp16 [Wn^T ; Wc^T], K-major [256][128]
__device__ float  g_sum[CC];            // zeroed by scan tail block
__device__ float  g_sumsq[CC];

// ---------------------------------------------------------------
// Kernel 1: scan (blocks 0..2047, R13-proven) + tails:
//   2048..2079 weight transpose->fp16, 2080 stat zero, 2081..2112 X->fp16.
__global__ void __launch_bounds__(256, 8)
k_scan(const uint4* __restrict__ A4,
       const float* __restrict__ Wn, const float* __restrict__ Wc,
       const float4* __restrict__ X4) {
    if (blockIdx.x >= SCANB) {
        int bid = blockIdx.x - SCANB;
        if (bid < 32) {
            __shared__ float s[32][33];
            int m = bid >> 4;
            int t = bid & 15;
            int tr = (t >> 2) * 32;
            int tc = (t & 3) * 32;
            const float* src = m ? Wc : Wn;
            __half* dst = g_BTh + m * CC * CC;
            int x = threadIdx.x & 31;
            int y0 = threadIdx.x >> 5;
#pragma unroll
            for (int dy = 0; dy < 32; dy += 8)
                s[y0 + dy][x] = src[(tr + y0 + dy) * CC + tc + x];
            __syncthreads();
#pragma unroll
            for (int dy = 0; dy < 32; dy += 8)
                dst[(tc + y0 + dy) * CC + tr + x] = __float2half(s[x][y0 + dy]);
        } else if (bid == 32) {
            if (threadIdx.x < CC) { g_sum[threadIdx.x] = 0.f; g_sumsq[threadIdx.x] = 0.f; }
        } else {
            int base = (bid - 33) * 8192 + threadIdx.x;
            uint2* dst = (uint2*)g_x16;
#pragma unroll
            for (int k = 0; k < 32; ++k) {
                int idx = base + k * 256;
                float4 v = __ldg(X4 + idx);
                __half2 h01 = __floats2half2_rn(v.x, v.y);
                __half2 h23 = __floats2half2_rn(v.z, v.w);
                uint2 p;
                p.x = *(unsigned*)&h01;
                p.y = *(unsigned*)&h23;
                dst[idx] = p;
            }
        }
        return;
    }

    const int lane = threadIdx.x & 31;
    const unsigned stride = SCANB * 256u;
    unsigned q0 = blockIdx.x * 256u + threadIdx.x;

#pragma unroll 1
    for (int it = 0; it < 8; ++it, q0 += 4u * stride) {
        uint4 v[4];
#pragma unroll
        for (int u = 0; u < 4; ++u) v[u] = __ldcs(&A4[q0 + u * stride]);
#pragma unroll
        for (int u = 0; u < 4; ++u) {
            unsigned nz = v[u].x | v[u].y | v[u].z | v[u].w;
            unsigned anyb = __ballot_sync(FULLMASK, nz != 0u);
            if (!anyb) continue;
            unsigned qu = q0 + u * stride;
            int j = (int)(qu >> 11);
            int cnt = (v[u].x != 0u) + (v[u].y != 0u) + (v[u].z != 0u) + (v[u].w != 0u);
            int tot = __reduce_add_sync(FULLMASK, cnt);
            if (lane == 0) atomicAdd(&g_degi[j], tot);
            if (nz) {
                unsigned cbase = (qu & 2047u) * 4u;
                unsigned vv[4] = {v[u].x, v[u].y, v[u].z, v[u].w};
#pragma unroll
                for (int s = 0; s < 4; ++s) {
                    if (vv[s]) {
                        unsigned i = cbase + s;
                        int pos = atomicAdd(&g_cnt[i], 1);
                        if (pos < CAP) g_bkt[i * CAP + pos] = j;
                    }
                }
            }
        }
    }
}

// ---------------------------------------------------------------
__device__ __forceinline__ void acc_h4(float4& a, uint2 p) {
    float2 lo = __half22float2(*(__half2*)&p.x);
    float2 hi = __half22float2(*(__half2*)&p.y);
    a.x += lo.x; a.y += lo.y; a.z += hi.x; a.w += hi.y;
}

// ---------------------------------------------------------------
// Kernel 2: fused gather (fp16) + wmma GEMM (fp16 in, fp32 acc) + BN stats.
// Block = 32 rows x 128 cols, 256 threads (8 warps), ~86KB smem -> 2/SM.
// A tile = [agg | X16] fp16 [32][256]; B = fp16 weights [256][128].
__global__ void __launch_bounds__(256, 2)
k_gemm(const float* __restrict__ bn, const float* __restrict__ bc) {
    extern __shared__ char shm[];
    __half* Bs = (__half*)shm;                    // [256][B_LD]
    __half* As = (__half*)(shm + B_BYTES);        // [32][AK_LD]
    float*  Cs = (float*)As;                      // reused after mainloop [32][C_LD]

    const int tid  = threadIdx.x;
    const int lane = tid & 31;
    const int wid  = tid >> 5;       // 8 warps
    const int m0   = blockIdx.x * BM;

    // --- stage fp16 weights (both halves) with padding ---
    {
        const uint4* src = (const uint4*)g_BTh;
#pragma unroll
        for (int i = 0; i < 16; ++i) {
            int idx = tid + i * 256;             // 0..4095
            int row = idx >> 4, c8 = (idx & 15) * 8;
            *(uint4*)(Bs + row * B_LD + c8) = __ldg(src + idx);
        }
        // stage X16 tile into A columns 128..255
        const uint4* xsrc = (const uint4*)(g_x16 + (size_t)m0 * CC);
#pragma unroll
        for (int i = 0; i < 2; ++i) {
            int idx = tid + i * 256;             // 0..511
            int row = idx >> 4, c8 = (idx & 15) * 8;
            *(uint4*)(As + row * AK_LD + 128 + c8) = __ldg(xsrc + idx);
        }
    }

    // --- gather: warp handles rows wid*4..+3, pairs, MLP 8 (R16-proven) ---
    const uint2* H2 = (const uint2*)g_x16;
#pragma unroll 1
    for (int rp = 0; rp < 4; rp += 2) {
        const int rowA = wid * 4 + rp, rowB = rowA + 1;
        const int nodeA = m0 + rowA,   nodeB = m0 + rowB;
        int cA = g_cnt[nodeA]; cA = cA > CAP ? CAP : cA;
        int cB = g_cnt[nodeB]; cB = cB > CAP ? CAP : cB;
        int dA = g_degi[nodeA], dB = g_degi[nodeB];
        float rA = (dA > 0) ? (1.f / (float)dA) : 1.f;
        float rB = (dB > 0) ? (1.f / (float)dB) : 1.f;
        const int* bkA = g_bkt + nodeA * CAP;
        const int* bkB = g_bkt + nodeB * CAP;

        int nbA[4], nbB[4];
#pragma unroll
        for (int w = 0; w < 4; ++w) {
            nbA[w] = (lane + 32 * w < cA) ? bkA[lane + 32 * w] : 0;
            nbB[w] = (lane + 32 * w < cB) ? bkB[lane + 32 * w] : 0;
        }

        float4 aA = {0.f, 0.f, 0.f, 0.f};
        float4 aB = {0.f, 0.f, 0.f, 0.f};
        const int mm = (cA < cB ? cA : cB) & ~3;
        int t = 0;
        for (; t < mm; t += 4) {
            int ja0 = __shfl_sync(FULLMASK, nbA[(t + 0) >> 5], (t + 0) & 31);
            int ja1 = __shfl_sync(FULLMASK, nbA[(t + 1) >> 5], (t + 1) & 31);
            int ja2 = __shfl_sync(FULLMASK, nbA[(t + 2) >> 5], (t + 2) & 31);
            int ja3 = __shfl_sync(FULLMASK, nbA[(t + 3) >> 5], (t + 3) & 31);
            int jb0 = __shfl_sync(FULLMASK, nbB[(t + 0) >> 5], (t + 0) & 31);
            int jb1 = __shfl_sync(FULLMASK, nbB[(t + 1) >> 5], (t + 1) & 31);
            int jb2 = __shfl_sync(FULLMASK, nbB[(t + 2) >> 5], (t + 2) & 31);
            int jb3 = __shfl_sync(FULLMASK, nbB[(t + 3) >> 5], (t + 3) & 31);
            uint2 x0 = __ldg(H2 + (long)ja0 * 32 + lane);
            uint2 x1 = __ldg(H2 + (long)ja1 * 32 + lane);
            uint2 x2 = __ldg(H2 + (long)ja2 * 32 + lane);
            uint2 x3 = __ldg(H2 + (long)ja3 * 32 + lane);
            uint2 y0 = __ldg(H2 + (long)jb0 * 32 + lane);
            uint2 y1 = __ldg(H2 + (long)jb1 * 32 + lane);
            uint2 y2 = __ldg(H2 + (long)jb2 * 32 + lane);
            uint2 y3 = __ldg(H2 + (long)jb3 * 32 + lane);
            acc_h4(aA, x0); acc_h4(aA, x1); acc_h4(aA, x2); acc_h4(aA, x3);
            acc_h4(aB, y0); acc_h4(aB, y1); acc_h4(aB, y2); acc_h4(aB, y3);
        }
        int tB = t;
        for (; t + 4 <= cA; t += 4) {
            int j0 = __shfl_sync(FULLMASK, nbA[(t + 0) >> 5], (t + 0) & 31);
            int j1 = __shfl_sync(FULLMASK, nbA[(t + 1) >> 5], (t + 1) & 31);
            int j2 = __shfl_sync(FULLMASK, nbA[(t + 2) >> 5], (t + 2) & 31);
            int j3 = __shfl_sync(FULLMASK, nbA[(t + 3) >> 5], (t + 3) & 31);
            uint2 x0 = __ldg(H2 + (long)j0 * 32 + lane);
            uint2 x1 = __ldg(H2 + (long)j1 * 32 + lane);
            uint2 x2 = __ldg(H2 + (long)j2 * 32 + lane);
            uint2 x3 = __ldg(H2 + (long)j3 * 32 + lane);
            acc_h4(aA, x0); acc_h4(aA, x1); acc_h4(aA, x2); acc_h4(aA, x3);
        }
        for (; t < cA; ++t) {
            int j = __shfl_sync(FULLMASK, nbA[t >> 5], t & 31);
            acc_h4(aA, __ldg(H2 + (long)j * 32 + lane));
        }
        for (; tB + 4 <= cB; tB += 4) {
            int j0 = __shfl_sync(FULLMASK, nbB[(tB + 0) >> 5], (tB + 0) & 31);
            int j1 = __shfl_sync(FULLMASK, nbB[(tB + 1) >> 5], (tB + 1) & 31);
            int j2 = __shfl_sync(FULLMASK, nbB[(tB + 2) >> 5], (tB + 2) & 31);
            int j3 = __shfl_sync(FULLMASK, nbB[(tB + 3) >> 5], (tB + 3) & 31);
            uint2 y0 = __ldg(H2 + (long)j0 * 32 + lane);
            uint2 y1 = __ldg(H2 + (long)j1 * 32 + lane);
            uint2 y2 = __ldg(H2 + (long)j2 * 32 + lane);
            uint2 y3 = __ldg(H2 + (long)j3 * 32 + lane);
            acc_h4(aB, y0); acc_h4(aB, y1); acc_h4(aB, y2); acc_h4(aB, y3);
        }
        for (; tB < cB; ++tB) {
            int j = __shfl_sync(FULLMASK, nbB[tB >> 5], tB & 31);
            acc_h4(aB, __ldg(H2 + (long)j * 32 + lane));
        }
        aA.x *= rA; aA.y *= rA; aA.z *= rA; aA.w *= rA;
        aB.x *= rB; aB.y *= rB; aB.z *= rB; aB.w *= rB;
        // store fp16 into A tile columns 0..127
        __half2 a01 = __floats2half2_rn(aA.x, aA.y);
        __half2 a23 = __floats2half2_rn(aA.z, aA.w);
        __half2 b01 = __floats2half2_rn(aB.x, aB.y);
        __half2 b23 = __floats2half2_rn(aB.z, aB.w);
        uint2 pa = {*(unsigned*)&a01, *(unsigned*)&a23};
        uint2 pb = {*(unsigned*)&b01, *(unsigned*)&b23};
        *(uint2*)(As + (size_t)rowA * AK_LD + lane * 4) = pa;
        *(uint2*)(As + (size_t)rowB * AK_LD + lane * 4) = pb;
    }
    if (lane < 4) {
        int node = m0 + wid * 4 + lane;
        g_cnt[node] = 0;
        g_degi[node] = 0;
    }
    __syncthreads();

    // --- wmma mainloop: warp w owns n-tile w (16 cols), both m-tiles ---
    wmma::fragment<wmma::matrix_a, 16, 16, 16, __half, wmma::row_major> af0, af1;
    wmma::fragment<wmma::matrix_b, 16, 16, 16, __half, wmma::row_major> bf;
    wmma::fragment<wmma::accumulator, 16, 16, 16, float> c0, c1;
    wmma::fill_fragment(c0, 0.f);
    wmma::fill_fragment(c1, 0.f);
    const int nt = wid;              // 0..7
#pragma unroll
    for (int kt = 0; kt < 16; ++kt) {
        wmma::load_matrix_sync(bf, Bs + kt * 16 * B_LD + nt * 16, B_LD);
        wmma::load_matrix_sync(af0, As + kt * 16, AK_LD);
        wmma::load_matrix_sync(af1, As + 16 * AK_LD + kt * 16, AK_LD);
        wmma::mma_sync(c0, af0, bf, c0);
        wmma::mma_sync(c1, af1, bf, c1);
    }
    __syncthreads();                 // all A/B reads done; reuse As as Cs
    wmma::store_matrix_sync(Cs + nt * 16, c0, C_LD, wmma::mem_row_major);
    wmma::store_matrix_sync(Cs + 16 * C_LD + nt * 16, c1, C_LD, wmma::mem_row_major);
    __syncthreads();

    // --- epilogue: bias, write h, BN stats ---
    float* s_sum = (float*)shm;
    float* s_sq  = (float*)shm + CC;
    if (tid < CC) { s_sum[tid] = 0.f; s_sq[tid] = 0.f; }
    __syncthreads();

    const int cg = tid & 31;         // cols cg*4..+3
    const int rg = tid >> 5;         // rows rg*4..+3
    float bias[4];
#pragma unroll
    for (int c = 0; c < 4; ++c) bias[c] = __ldg(bn + cg * 4 + c) + __ldg(bc + cg * 4 + c);

    float psum[4] = {0, 0, 0, 0};
    float psq[4]  = {0, 0, 0, 0};
#pragma unroll
    for (int r = 0; r < 4; ++r) {
        int ml = rg * 4 + r;
        float4 p = *(const float4*)(Cs + ml * C_LD + cg * 4);
        float h[4] = {p.x + bias[0], p.y + bias[1], p.z + bias[2], p.w + bias[3]};
#pragma unroll
        for (int c = 0; c < 4; ++c) { psum[c] += h[c]; psq[c] += h[c] * h[c]; }
        float4 hv = {h[0], h[1], h[2], h[3]};
        *(float4*)(g_h + (size_t)(m0 + ml) * CC + cg * 4) = hv;
    }
#pragma unroll
    for (int c = 0; c < 4; ++c) {
        atomicAdd(&s_sum[cg * 4 + c], psum[c]);
        atomicAdd(&s_sq[cg * 4 + c],  psq[c]);
    }
    __syncthreads();
    if (tid < CC) {
        atomicAdd(&g_sum[tid],   s_sum[tid]);
        atomicAdd(&g_sumsq[tid], s_sq[tid]);
    }
}

// ---------------------------------------------------------------
// Kernel 3: per-block scale/shift from BN stats (L2-hot) + normalize.
__global__ void k_norm(const float* __restrict__ gamma, const float* __restrict__ beta,
                       float* __restrict__ out) {
    __shared__ float s_sc[CC], s_sf[CC];
    const int tid = threadIdx.x;
    if (tid < CC) {
        const float invN = 1.f / (float)NN;
        float mu  = g_sum[tid] * invN;
        float var = fmaxf(g_sumsq[tid] * invN - mu * mu, 0.f);
        float inv = rsqrtf(var + 1e-5f);
        float sc = __ldg(gamma + tid) * inv;
        s_sc[tid] = sc;
        s_sf[tid] = __ldg(beta + tid) - mu * sc;
    }
    __syncthreads();

    const int gtid = blockIdx.x * blockDim.x + tid;
    const int c0 = (gtid & 31) * 4;
    float4 sc = *(const float4*)(s_sc + c0);
    float4 sf = *(const float4*)(s_sf + c0);
    const float4* hp = (const float4*)g_h;
    float4* op = (float4*)out;
#pragma unroll
    for (int u = 0; u < 2; ++u) {
        int idx = gtid + u * 131072;
        float4 h = __ldcs(hp + idx);
        float4 o;
        o.x = fmaxf(fmaf(h.x, sc.x, sf.x), 0.f);
        o.y = fmaxf(fmaf(h.y, sc.y, sf.y), 0.f);
        o.z = fmaxf(fmaf(h.z, sc.z, sf.z), 0.f);
        o.w = fmaxf(fmaf(h.w, sc.w, sf.w), 0.f);
        op[idx] = o;
    }
}

// ---------------------------------------------------------------
extern "C" void kernel_launch(void* const* d_in, const int* in_sizes, int n_in,
                              void* d_out, int out_size) {
    const float* Xf    = (const float*)d_in[0];
    const float* A     = (const float*)d_in[1];
    const float* Wn    = (const float*)d_in[2];
    const float* bn    = (const float*)d_in[3];
    const float* Wc    = (const float*)d_in[4];
    const float* bc    = (const float*)d_in[5];
    const float* gamma = (const float*)d_in[6];
    const float* beta  = (const float*)d_in[7];
    if (in_sizes[0] > in_sizes[1]) { const float* t = Xf; Xf = A; A = t; }

    float* out = (float*)d_out;

    static bool attr_done = []() {
        cudaFuncSetAttribute(k_gemm, cudaFuncAttributeMaxDynamicSharedMemorySize, SMEM_TOTAL);
        return true;
    }();
    (void)attr_done;

    k_scan<<<SCANB + 65, 256>>>((const uint4*)A, Wn, Wc, (const float4*)Xf);
    k_gemm<<<NN / BM, 256, SMEM_TOTAL>>>(bn, bc);
    k_norm<<<512, 256>>>(gamma, beta, out);
}